// round 1
// baseline (speedup 1.0000x reference)
#include <cuda_runtime.h>
#include <math.h>

// ---------------- problem constants (fixed shapes for this instance) -------
#define R_ROIS 2000
#define NOBJ   21
#define HFE    38
#define WFE    50
#define CCH    512
#define D1     25088        // 512*7*7
#define DH     4096
#define NACT   27
#define HUMAN_LBL 14        // label index (class 15 in cls_bbox)

#define SPLIT1 64
#define ROWS1  (D1/SPLIT1)  // 392
#define SPLIT2 32
#define ROWS2  (DH/SPLIT2)  // 128

// ---------------- device scratch (no allocations allowed) ------------------
__device__ float g_kept[20][4];   // one kept box per class label (feature coords, yxyx)
__device__ float g_hbox[4];       // human box
__device__ float g_feat[D1];      // roi-pooled features
__device__ float g_part1[SPLIT1 * DH];
__device__ float g_h1[DH];
__device__ float g_part2[SPLIT2 * DH];
__device__ float g_fc7[DH];
__device__ float g_loc[4];        // pred_object_loc

// ---------------------------------------------------------------------------
// Kernel 1: per-class argmax of softmax prob + box decode (NMS_T=0 => top-1)
// 20 blocks (one per label), 256 threads
// ---------------------------------------------------------------------------
__global__ void k_select(const float* __restrict__ scores,
                         const float* __restrict__ off,
                         const float* __restrict__ rois,
                         const int*   __restrict__ imgshape)
{
    const int l   = blockIdx.x;   // label 0..19
    const int cls = l + 1;        // class in 21-way head

    float best  = -1.0f;
    int   bestr = 0x7fffffff;
    for (int r = threadIdx.x; r < R_ROIS; r += blockDim.x) {
        const float* s = scores + r * NOBJ;
        float mx = s[0];
        #pragma unroll
        for (int j = 1; j < NOBJ; j++) mx = fmaxf(mx, s[j]);
        float sum = 0.0f;
        #pragma unroll
        for (int j = 0; j < NOBJ; j++) sum += expf(s[j] - mx);
        float p = expf(s[cls] - mx) / sum;
        if (p > best) { best = p; bestr = r; }   // ascending r => first max kept
    }

    __shared__ float sb[256];
    __shared__ int   si[256];
    sb[threadIdx.x] = best;
    si[threadIdx.x] = bestr;
    __syncthreads();
    for (int st = blockDim.x >> 1; st > 0; st >>= 1) {
        if (threadIdx.x < st) {
            float ob = sb[threadIdx.x + st];
            int   oi = si[threadIdx.x + st];
            if (ob > sb[threadIdx.x] ||
                (ob == sb[threadIdx.x] && oi < si[threadIdx.x])) {
                sb[threadIdx.x] = ob; si[threadIdx.x] = oi;
            }
        }
        __syncthreads();
    }

    if (threadIdx.x == 0) {
        const int r = si[0];
        const float img0 = (float)imgshape[0];
        const float img1 = (float)imgshape[1];
        const float sy = (float)HFE / img0;
        const float sx = (float)WFE / img1;
        const float y1 = rois[r * 4 + 0] * sy;
        const float x1 = rois[r * 4 + 1] * sx;
        const float y2 = rois[r * 4 + 2] * sy;
        const float x2 = rois[r * 4 + 3] * sx;
        const float dy = off[r * (NOBJ * 4) + cls * 4 + 0] * 0.1f;
        const float dx = off[r * (NOBJ * 4) + cls * 4 + 1] * 0.1f;
        const float dh = off[r * (NOBJ * 4) + cls * 4 + 2] * 0.2f;
        const float dw = off[r * (NOBJ * 4) + cls * 4 + 3] * 0.2f;
        const float h  = y2 - y1, w = x2 - x1;
        const float cy = y1 + 0.5f * h, cx = x1 + 0.5f * w;
        const float cy2 = dy * h + cy, cx2 = dx * w + cx;
        const float h2 = expf(dh) * h, w2 = expf(dw) * w;
        float by1 = fminf(fmaxf(cy2 - 0.5f * h2, 0.0f), (float)HFE);
        float bx1 = fminf(fmaxf(cx2 - 0.5f * w2, 0.0f), (float)WFE);
        float by2 = fminf(fmaxf(cy2 + 0.5f * h2, 0.0f), (float)HFE);
        float bx2 = fminf(fmaxf(cx2 + 0.5f * w2, 0.0f), (float)WFE);
        g_kept[l][0] = by1; g_kept[l][1] = bx1;
        g_kept[l][2] = by2; g_kept[l][3] = bx2;
        if (l == HUMAN_LBL) {
            g_hbox[0] = by1; g_hbox[1] = bx1;
            g_hbox[2] = by2; g_hbox[3] = bx2;
        }
    }
}

// ---------------------------------------------------------------------------
// Kernel 2: chainer-style RoIPooling2D on the human box
// 25088 threads, one per output element
// ---------------------------------------------------------------------------
__global__ void k_roipool(const float* __restrict__ x)
{
    const int idx = blockIdx.x * blockDim.x + threadIdx.x;
    if (idx >= D1) return;
    const int c  = idx / 49;
    const int ph = (idx % 49) / 7;
    const int pw = idx % 7;

    const float y1 = g_hbox[0], x1 = g_hbox[1], y2 = g_hbox[2], x2 = g_hbox[3];
    // jnp.round == round-half-to-even == rintf
    const int xmin = (int)rintf(x1 * 0.0625f);
    const int ymin = (int)rintf(y1 * 0.0625f);
    const int xmax = (int)rintf(x2 * 0.0625f);
    const int ymax = (int)rintf(y2 * 0.0625f);
    const float rw = (float)max(xmax - xmin + 1, 1);
    const float rh = (float)max(ymax - ymin + 1, 1);

    int hs = ymin + (int)floorf((float)ph * rh / 7.0f);
    int he = ymin + (int)ceilf((float)(ph + 1) * rh / 7.0f);
    int ws = xmin + (int)floorf((float)pw * rw / 7.0f);
    int we = xmin + (int)ceilf((float)(pw + 1) * rw / 7.0f);
    hs = min(max(hs, 0), HFE); he = min(max(he, 0), HFE);
    ws = min(max(ws, 0), WFE); we = min(max(we, 0), WFE);

    float m = -1e30f;
    for (int yy = hs; yy < he; yy++)
        for (int xx = ws; xx < we; xx++)
            m = fmaxf(m, x[c * (HFE * WFE) + yy * WFE + xx]);
    g_feat[idx] = (hs < he && ws < we) ? ((m <= -0.5e30f) ? 0.0f : m) : 0.0f;
}

// ---------------------------------------------------------------------------
// Kernel 3: GEMV1 split-K.  grid (DH/128, SPLIT1), block 128.
// thread j reads W1[i*4096 + j] -> fully coalesced, 512B/warp/row
// ---------------------------------------------------------------------------
__global__ void k_gemv1(const float* __restrict__ W1)
{
    const int j  = blockIdx.x * 128 + threadIdx.x;
    const int i0 = blockIdx.y * ROWS1;

    __shared__ float sf[ROWS1];
    for (int t = threadIdx.x; t < ROWS1; t += 128) sf[t] = g_feat[i0 + t];
    __syncthreads();

    float acc = 0.0f;
    const float* __restrict__ w = W1 + (size_t)i0 * DH + j;
    #pragma unroll 8
    for (int i = 0; i < ROWS1; i++)
        acc += sf[i] * w[(size_t)i * DH];
    g_part1[blockIdx.y * DH + j] = acc;
}

__global__ void k_reduce1(const float* __restrict__ b1)
{
    const int j = blockIdx.x * blockDim.x + threadIdx.x;
    if (j >= DH) return;
    float s = b1[j];
    #pragma unroll 8
    for (int k = 0; k < SPLIT1; k++) s += g_part1[k * DH + j];
    g_h1[j] = fmaxf(s, 0.0f);
}

// ---------------------------------------------------------------------------
// Kernel 5: GEMV2 split-K.  grid (DH/128, SPLIT2), block 128.
// ---------------------------------------------------------------------------
__global__ void k_gemv2(const float* __restrict__ W2)
{
    const int j  = blockIdx.x * 128 + threadIdx.x;
    const int i0 = blockIdx.y * ROWS2;

    __shared__ float sf[ROWS2];
    if (threadIdx.x < ROWS2) sf[threadIdx.x] = g_h1[i0 + threadIdx.x];
    __syncthreads();

    float acc = 0.0f;
    const float* __restrict__ w = W2 + (size_t)i0 * DH + j;
    #pragma unroll 8
    for (int i = 0; i < ROWS2; i++)
        acc += sf[i] * w[(size_t)i * DH];
    g_part2[blockIdx.y * DH + j] = acc;
}

__global__ void k_reduce2(const float* __restrict__ b2)
{
    const int j = blockIdx.x * blockDim.x + threadIdx.x;
    if (j >= DH) return;
    float s = b2[j];
    #pragma unroll 8
    for (int k = 0; k < SPLIT2; k++) s += g_part2[k * DH + j];
    g_fc7[j] = fmaxf(s, 0.0f);
}

// ---------------------------------------------------------------------------
// Kernel 7: heads. 31 blocks (4 loc + 27 act), 256 threads each.
// ---------------------------------------------------------------------------
__global__ void k_heads(const float* __restrict__ Wloc, const float* __restrict__ bloc,
                        const float* __restrict__ Wact, const float* __restrict__ bact,
                        float* __restrict__ out)
{
    const int o = blockIdx.x;   // 0..30
    float acc = 0.0f;
    if (o < 4) {
        for (int i = threadIdx.x; i < DH; i += 256)
            acc += g_fc7[i] * Wloc[i * 4 + o];
    } else {
        const int a = o - 4;
        for (int i = threadIdx.x; i < DH; i += 256)
            acc += g_fc7[i] * Wact[i * NACT + a];
    }
    __shared__ float sb[256];
    sb[threadIdx.x] = acc;
    __syncthreads();
    for (int st = 128; st > 0; st >>= 1) {
        if (threadIdx.x < st) sb[threadIdx.x] += sb[threadIdx.x + st];
        __syncthreads();
    }
    if (threadIdx.x == 0) {
        if (o < 4) g_loc[o] = sb[0] + bloc[o];
        else       out[8 + (o - 4)] = sb[0] + bact[o - 4];   // action scores
    }
}

// ---------------------------------------------------------------------------
// Kernel 8: gaussian object selection + output assembly (tiny, single warp)
// ---------------------------------------------------------------------------
__global__ void k_final(const int* __restrict__ imgshape, float* __restrict__ out)
{
    if (threadIdx.x != 0) return;
    const float img0 = (float)imgshape[0];
    const float img1 = (float)imgshape[1];

    const float hb0 = g_hbox[0], hb1 = g_hbox[1], hb2 = g_hbox[2], hb3 = g_hbox[3];
    const float hw_ = hb3 - hb1, hh_ = hb2 - hb0;
    const float h4x = 0.5f * hw_, h4y = 0.5f * hh_;
    const float hw = fmaxf(hw_, 1e-3f), hh = fmaxf(hh_, 1e-3f);

    const float mw = g_loc[3] - g_loc[1], mh = g_loc[2] - g_loc[0];
    const float mu0 = 0.5f * mw, mu1 = 0.5f * mh, mu2 = mw, mu3 = mh;

    float best = -1.0f;
    int   bl   = 0;
    for (int l = 0; l < 20; l++) {
        if (l == HUMAN_LBL) continue;
        const float b0 = g_kept[l][0], b1 = g_kept[l][1];
        const float b2 = g_kept[l][2], b3 = g_kept[l][3];
        const float cw_ = b3 - b1, ch_ = b2 - b0;
        const float cx = 0.5f * cw_, cy = 0.5f * ch_;
        const float cw = fmaxf(cw_, 1e-3f), ch = fmaxf(ch_, 1e-3f);
        const float d0 = (cx - h4x) / hw - mu0;
        const float d1 = (cy - h4y) / hh - mu1;
        const float d2 = logf(cw / hw) - mu2;
        const float d3 = logf(ch / hh) - mu3;
        const float gau = expf(-(d0 * d0 + d1 * d1 + d2 * d2 + d3 * d3) /
                               (2.0f * 0.3f * 0.3f));
        if (gau > best) { best = gau; bl = l; }  // ascending l == lowest flat index
    }

    const float invy = img0 / (float)HFE;
    const float invx = img1 / (float)WFE;
    out[0] = hb0 * invy; out[1] = hb1 * invx;
    out[2] = hb2 * invy; out[3] = hb3 * invx;
    out[4] = g_kept[bl][0] * invy; out[5] = g_kept[bl][1] * invx;
    out[6] = g_kept[bl][2] * invy; out[7] = g_kept[bl][3] * invx;
    out[35] = (float)HFE / img0;   // my_scale
}

// ---------------------------------------------------------------------------
extern "C" void kernel_launch(void* const* d_in, const int* in_sizes, int n_in,
                              void* d_out, int out_size)
{
    const float* x        = (const float*)d_in[0];
    const float* pscores  = (const float*)d_in[1];
    const float* poff     = (const float*)d_in[2];
    const float* rois     = (const float*)d_in[3];
    const int*   imgshape = (const int*)  d_in[4];
    const float* W1       = (const float*)d_in[5];
    const float* b1       = (const float*)d_in[6];
    const float* W2       = (const float*)d_in[7];
    const float* b2       = (const float*)d_in[8];
    const float* Wloc     = (const float*)d_in[9];
    const float* bloc     = (const float*)d_in[10];
    const float* Wact     = (const float*)d_in[11];
    const float* bact     = (const float*)d_in[12];
    float* out = (float*)d_out;

    k_select <<<20, 256>>>(pscores, poff, rois, imgshape);
    k_roipool<<<(D1 + 255) / 256, 256>>>(x);
    k_gemv1  <<<dim3(DH / 128, SPLIT1), 128>>>(W1);
    k_reduce1<<<DH / 256, 256>>>(b1);
    k_gemv2  <<<dim3(DH / 128, SPLIT2), 128>>>(W2);
    k_reduce2<<<DH / 256, 256>>>(b2);
    k_heads  <<<31, 256>>>(Wloc, bloc, Wact, bact, out);
    k_final  <<<1, 32>>>(imgshape, out);
}

// round 2
// speedup vs baseline: 1.0411x; 1.0411x over previous
#include <cuda_runtime.h>
#include <math.h>

// ---------------- problem constants (fixed shapes for this instance) -------
#define R_ROIS 2000
#define NOBJ   21
#define HFE    38
#define WFE    50
#define CCH    512
#define D1     25088        // 512*7*7
#define DH     4096
#define NACT   27
#define HUMAN_LBL 14        // label index (class 15 in cls_bbox)

#define SPLIT1 64
#define ROWS1  (D1/SPLIT1)  // 392
#define SPLIT2 32
#define ROWS2  (DH/SPLIT2)  // 128

// ---------------- device scratch (no allocations allowed) ------------------
__device__ float g_logZ[R_ROIS]; // per-roi  max + log(sum(exp(s - max)))
__device__ float g_kept[20][4];  // one kept box per class label (feature coords)
__device__ float g_hbox[4];      // human box
__device__ float g_feat[D1];     // roi-pooled features
__device__ float g_part1[SPLIT1 * DH];
__device__ float g_h1[DH];
__device__ float g_part2[SPLIT2 * DH];
__device__ float g_fc7[DH];
__device__ float g_loc[4];       // pred_object_loc

// ---------------------------------------------------------------------------
// Kernel 0: per-roi softmax log-normalizer (one thread per roi)
// ---------------------------------------------------------------------------
__global__ void k_softprep(const float* __restrict__ scores)
{
    const int r = blockIdx.x * blockDim.x + threadIdx.x;
    if (r >= R_ROIS) return;
    const float* s = scores + r * NOBJ;
    float mx = s[0];
    #pragma unroll
    for (int j = 1; j < NOBJ; j++) mx = fmaxf(mx, s[j]);
    float sum = 0.0f;
    #pragma unroll
    for (int j = 0; j < NOBJ; j++) sum += expf(s[j] - mx);
    g_logZ[r] = mx + logf(sum);
}

// ---------------------------------------------------------------------------
// Kernel 1: per-class argmax (NMS_T=0 => greedy NMS keeps only top-1/class)
// argmax_r softmax(s)[cls] == argmax_r (s[cls] - logZ[r])  (monotone)
// 20 blocks (one per label), 256 threads
// ---------------------------------------------------------------------------
__global__ void k_select(const float* __restrict__ scores,
                         const float* __restrict__ off,
                         const float* __restrict__ rois,
                         const int*   __restrict__ imgshape)
{
    const int l   = blockIdx.x;   // label 0..19
    const int cls = l + 1;        // class in 21-way head

    float best  = -1e30f;
    int   bestr = 0x7fffffff;
    for (int r = threadIdx.x; r < R_ROIS; r += blockDim.x) {
        const float t = scores[r * NOBJ + cls] - g_logZ[r];
        if (t > best) { best = t; bestr = r; }   // ascending r => first max kept
    }

    __shared__ float sb[256];
    __shared__ int   si[256];
    sb[threadIdx.x] = best;
    si[threadIdx.x] = bestr;
    __syncthreads();
    for (int st = blockDim.x >> 1; st > 0; st >>= 1) {
        if (threadIdx.x < st) {
            float ob = sb[threadIdx.x + st];
            int   oi = si[threadIdx.x + st];
            if (ob > sb[threadIdx.x] ||
                (ob == sb[threadIdx.x] && oi < si[threadIdx.x])) {
                sb[threadIdx.x] = ob; si[threadIdx.x] = oi;
            }
        }
        __syncthreads();
    }

    if (threadIdx.x == 0) {
        const int r = si[0];
        const float img0 = (float)imgshape[0];
        const float img1 = (float)imgshape[1];
        const float sy = (float)HFE / img0;
        const float sx = (float)WFE / img1;
        const float y1 = rois[r * 4 + 0] * sy;
        const float x1 = rois[r * 4 + 1] * sx;
        const float y2 = rois[r * 4 + 2] * sy;
        const float x2 = rois[r * 4 + 3] * sx;
        const float dy = off[r * (NOBJ * 4) + cls * 4 + 0] * 0.1f;
        const float dx = off[r * (NOBJ * 4) + cls * 4 + 1] * 0.1f;
        const float dh = off[r * (NOBJ * 4) + cls * 4 + 2] * 0.2f;
        const float dw = off[r * (NOBJ * 4) + cls * 4 + 3] * 0.2f;
        const float h  = y2 - y1, w = x2 - x1;
        const float cy = y1 + 0.5f * h, cx = x1 + 0.5f * w;
        const float cy2 = dy * h + cy, cx2 = dx * w + cx;
        const float h2 = expf(dh) * h, w2 = expf(dw) * w;
        float by1 = fminf(fmaxf(cy2 - 0.5f * h2, 0.0f), (float)HFE);
        float bx1 = fminf(fmaxf(cx2 - 0.5f * w2, 0.0f), (float)WFE);
        float by2 = fminf(fmaxf(cy2 + 0.5f * h2, 0.0f), (float)HFE);
        float bx2 = fminf(fmaxf(cx2 + 0.5f * w2, 0.0f), (float)WFE);
        g_kept[l][0] = by1; g_kept[l][1] = bx1;
        g_kept[l][2] = by2; g_kept[l][3] = bx2;
        if (l == HUMAN_LBL) {
            g_hbox[0] = by1; g_hbox[1] = bx1;
            g_hbox[2] = by2; g_hbox[3] = bx2;
        }
    }
}

// ---------------------------------------------------------------------------
// Kernel 2: chainer-style RoIPooling2D on the human box
// ---------------------------------------------------------------------------
__global__ void k_roipool(const float* __restrict__ x)
{
    const int idx = blockIdx.x * blockDim.x + threadIdx.x;
    if (idx >= D1) return;
    const int c  = idx / 49;
    const int ph = (idx % 49) / 7;
    const int pw = idx % 7;

    const float y1 = g_hbox[0], x1 = g_hbox[1], y2 = g_hbox[2], x2 = g_hbox[3];
    const int xmin = (int)rintf(x1 * 0.0625f);
    const int ymin = (int)rintf(y1 * 0.0625f);
    const int xmax = (int)rintf(x2 * 0.0625f);
    const int ymax = (int)rintf(y2 * 0.0625f);
    const float rw = (float)max(xmax - xmin + 1, 1);
    const float rh = (float)max(ymax - ymin + 1, 1);

    int hs = ymin + (int)floorf((float)ph * rh / 7.0f);
    int he = ymin + (int)ceilf((float)(ph + 1) * rh / 7.0f);
    int ws = xmin + (int)floorf((float)pw * rw / 7.0f);
    int we = xmin + (int)ceilf((float)(pw + 1) * rw / 7.0f);
    hs = min(max(hs, 0), HFE); he = min(max(he, 0), HFE);
    ws = min(max(ws, 0), WFE); we = min(max(we, 0), WFE);

    float m = -1e30f;
    for (int yy = hs; yy < he; yy++)
        for (int xx = ws; xx < we; xx++)
            m = fmaxf(m, x[c * (HFE * WFE) + yy * WFE + xx]);
    g_feat[idx] = (hs < he && ws < we) ? ((m <= -0.5e30f) ? 0.0f : m) : 0.0f;
}

// ---------------------------------------------------------------------------
// Kernel 3: GEMV1 split-K.  grid (DH/128, SPLIT1), block 128.
// ---------------------------------------------------------------------------
__global__ void k_gemv1(const float* __restrict__ W1)
{
    const int j  = blockIdx.x * 128 + threadIdx.x;
    const int i0 = blockIdx.y * ROWS1;

    __shared__ float sf[ROWS1];
    for (int t = threadIdx.x; t < ROWS1; t += 128) sf[t] = g_feat[i0 + t];
    __syncthreads();

    float acc = 0.0f;
    const float* __restrict__ w = W1 + (size_t)i0 * DH + j;
    #pragma unroll 8
    for (int i = 0; i < ROWS1; i++)
        acc += sf[i] * w[(size_t)i * DH];
    g_part1[blockIdx.y * DH + j] = acc;
}

// ---------------------------------------------------------------------------
// Kernel 4: reduce1. 64 blocks x 256 threads: 64 j per block, 4 k-chunks of 16
// ---------------------------------------------------------------------------
__global__ void k_reduce1(const float* __restrict__ b1)
{
    const int jl = threadIdx.x & 63;     // 0..63
    const int kq = threadIdx.x >> 6;     // 0..3
    const int j  = blockIdx.x * 64 + jl;

    float s = 0.0f;
    #pragma unroll
    for (int k = 0; k < SPLIT1 / 4; k++)
        s += g_part1[(kq * (SPLIT1 / 4) + k) * DH + j];

    __shared__ float sm[4][64];
    sm[kq][jl] = s;
    __syncthreads();
    if (kq == 0) {
        float t = sm[0][jl] + sm[1][jl] + sm[2][jl] + sm[3][jl] + b1[j];
        g_h1[j] = fmaxf(t, 0.0f);
    }
}

// ---------------------------------------------------------------------------
// Kernel 5: GEMV2 split-K.  grid (DH/128, SPLIT2), block 128.
// ---------------------------------------------------------------------------
__global__ void k_gemv2(const float* __restrict__ W2)
{
    const int j  = blockIdx.x * 128 + threadIdx.x;
    const int i0 = blockIdx.y * ROWS2;

    __shared__ float sf[ROWS2];
    if (threadIdx.x < ROWS2) sf[threadIdx.x] = g_h1[i0 + threadIdx.x];
    __syncthreads();

    float acc = 0.0f;
    const float* __restrict__ w = W2 + (size_t)i0 * DH + j;
    #pragma unroll 8
    for (int i = 0; i < ROWS2; i++)
        acc += sf[i] * w[(size_t)i * DH];
    g_part2[blockIdx.y * DH + j] = acc;
}

// ---------------------------------------------------------------------------
// Kernel 6: reduce2. 64 blocks x 256 threads: 64 j per block, 4 k-chunks of 8
// ---------------------------------------------------------------------------
__global__ void k_reduce2(const float* __restrict__ b2)
{
    const int jl = threadIdx.x & 63;
    const int kq = threadIdx.x >> 6;
    const int j  = blockIdx.x * 64 + jl;

    float s = 0.0f;
    #pragma unroll
    for (int k = 0; k < SPLIT2 / 4; k++)
        s += g_part2[(kq * (SPLIT2 / 4) + k) * DH + j];

    __shared__ float sm[4][64];
    sm[kq][jl] = s;
    __syncthreads();
    if (kq == 0) {
        float t = sm[0][jl] + sm[1][jl] + sm[2][jl] + sm[3][jl] + b2[j];
        g_fc7[j] = fmaxf(t, 0.0f);
    }
}

// ---------------------------------------------------------------------------
// Kernel 7: heads. 31 blocks (4 loc + 27 act), 256 threads each.
// ---------------------------------------------------------------------------
__global__ void k_heads(const float* __restrict__ Wloc, const float* __restrict__ bloc,
                        const float* __restrict__ Wact, const float* __restrict__ bact,
                        float* __restrict__ out)
{
    const int o = blockIdx.x;   // 0..30
    float acc = 0.0f;
    if (o < 4) {
        for (int i = threadIdx.x; i < DH; i += 256)
            acc += g_fc7[i] * Wloc[i * 4 + o];
    } else {
        const int a = o - 4;
        for (int i = threadIdx.x; i < DH; i += 256)
            acc += g_fc7[i] * Wact[i * NACT + a];
    }
    __shared__ float sb[256];
    sb[threadIdx.x] = acc;
    __syncthreads();
    for (int st = 128; st > 0; st >>= 1) {
        if (threadIdx.x < st) sb[threadIdx.x] += sb[threadIdx.x + st];
        __syncthreads();
    }
    if (threadIdx.x == 0) {
        if (o < 4) g_loc[o] = sb[0] + bloc[o];
        else       out[8 + (o - 4)] = sb[0] + bact[o - 4];   // action scores
    }
}

// ---------------------------------------------------------------------------
// Kernel 8: gaussian object selection + output assembly (tiny)
// ---------------------------------------------------------------------------
__global__ void k_final(const int* __restrict__ imgshape, float* __restrict__ out)
{
    if (threadIdx.x != 0) return;
    const float img0 = (float)imgshape[0];
    const float img1 = (float)imgshape[1];

    const float hb0 = g_hbox[0], hb1 = g_hbox[1], hb2 = g_hbox[2], hb3 = g_hbox[3];
    const float hw_ = hb3 - hb1, hh_ = hb2 - hb0;
    const float h4x = 0.5f * hw_, h4y = 0.5f * hh_;
    const float hw = fmaxf(hw_, 1e-3f), hh = fmaxf(hh_, 1e-3f);

    const float mw = g_loc[3] - g_loc[1], mh = g_loc[2] - g_loc[0];
    const float mu0 = 0.5f * mw, mu1 = 0.5f * mh, mu2 = mw, mu3 = mh;

    float best = -1.0f;
    int   bl   = 0;
    for (int l = 0; l < 20; l++) {
        if (l == HUMAN_LBL) continue;
        const float b0 = g_kept[l][0], b1 = g_kept[l][1];
        const float b2 = g_kept[l][2], b3 = g_kept[l][3];
        const float cw_ = b3 - b1, ch_ = b2 - b0;
        const float cx = 0.5f * cw_, cy = 0.5f * ch_;
        const float cw = fmaxf(cw_, 1e-3f), ch = fmaxf(ch_, 1e-3f);
        const float d0 = (cx - h4x) / hw - mu0;
        const float d1 = (cy - h4y) / hh - mu1;
        const float d2 = logf(cw / hw) - mu2;
        const float d3 = logf(ch / hh) - mu3;
        const float gau = expf(-(d0 * d0 + d1 * d1 + d2 * d2 + d3 * d3) /
                               (2.0f * 0.3f * 0.3f));
        if (gau > best) { best = gau; bl = l; }  // ascending l == lowest flat index
    }

    const float invy = img0 / (float)HFE;
    const float invx = img1 / (float)WFE;
    out[0] = hb0 * invy; out[1] = hb1 * invx;
    out[2] = hb2 * invy; out[3] = hb3 * invx;
    out[4] = g_kept[bl][0] * invy; out[5] = g_kept[bl][1] * invx;
    out[6] = g_kept[bl][2] * invy; out[7] = g_kept[bl][3] * invx;
    out[35] = (float)HFE / img0;   // my_scale
}

// ---------------------------------------------------------------------------
extern "C" void kernel_launch(void* const* d_in, const int* in_sizes, int n_in,
                              void* d_out, int out_size)
{
    const float* x        = (const float*)d_in[0];
    const float* pscores  = (const float*)d_in[1];
    const float* poff     = (const float*)d_in[2];
    const float* rois     = (const float*)d_in[3];
    const int*   imgshape = (const int*)  d_in[4];
    const float* W1       = (const float*)d_in[5];
    const float* b1       = (const float*)d_in[6];
    const float* W2       = (const float*)d_in[7];
    const float* b2       = (const float*)d_in[8];
    const float* Wloc     = (const float*)d_in[9];
    const float* bloc     = (const float*)d_in[10];
    const float* Wact     = (const float*)d_in[11];
    const float* bact     = (const float*)d_in[12];
    float* out = (float*)d_out;

    k_softprep<<<(R_ROIS + 255) / 256, 256>>>(pscores);
    k_select  <<<20, 256>>>(pscores, poff, rois, imgshape);
    k_roipool <<<(D1 + 255) / 256, 256>>>(x);
    k_gemv1   <<<dim3(DH / 128, SPLIT1), 128>>>(W1);
    k_reduce1 <<<64, 256>>>(b1);
    k_gemv2   <<<dim3(DH / 128, SPLIT2), 128>>>(W2);
    k_reduce2 <<<64, 256>>>(b2);
    k_heads   <<<31, 256>>>(Wloc, bloc, Wact, bact, out);
    k_final   <<<1, 32>>>(imgshape, out);
}

// round 3
// speedup vs baseline: 1.0646x; 1.0226x over previous
#include <cuda_runtime.h>
#include <math.h>

// ---------------- problem constants (fixed shapes for this instance) -------
#define R_ROIS 2000
#define NOBJ   21
#define HFE    38
#define WFE    50
#define D1     25088        // 512*7*7
#define DH     4096
#define DH4    (DH/4)       // 1024 float4 per row
#define NACT   27
#define HUMAN_LBL 14

#define SPLIT1 64
#define ROWS1  (D1/SPLIT1)  // 392
#define SPLIT2 32
#define ROWS2  (DH/SPLIT2)  // 128
#define PREF_BLKS 256       // W2 prefetch blocks inside gemv1
#define PREF_PER_BLK ((DH*DH/4)/PREF_BLKS)   // 16384 float4
#define PREF_PER_THR (PREF_PER_BLK/256)      // 64 float4

// ---------------- device scratch (no allocations allowed) ------------------
__device__ float  g_logZ[R_ROIS];
__device__ float  g_kept[20][4];
__device__ float  g_hbox[4];
__device__ float  g_feat[D1];
__device__ float4 g_part1[SPLIT1 * DH4];
__device__ float  g_h1[DH];
__device__ float4 g_part2[SPLIT2 * DH4];
__device__ float  g_fc7[DH];
__device__ float  g_loc[4];
__device__ float  g_sink[PREF_BLKS * 256];   // prefetch DCE guard (never read)

// ---------------------------------------------------------------------------
// Kernel 0: per-roi softmax log-normalizer
// ---------------------------------------------------------------------------
__global__ void k_softprep(const float* __restrict__ scores)
{
    const int r = blockIdx.x * blockDim.x + threadIdx.x;
    if (r >= R_ROIS) return;
    const float* s = scores + r * NOBJ;
    float mx = s[0];
    #pragma unroll
    for (int j = 1; j < NOBJ; j++) mx = fmaxf(mx, s[j]);
    float sum = 0.0f;
    #pragma unroll
    for (int j = 0; j < NOBJ; j++) sum += expf(s[j] - mx);
    g_logZ[r] = mx + logf(sum);
}

// ---------------------------------------------------------------------------
// Kernel 1: per-class argmax (NMS_T=0 => top-1 per class) + box decode
// ---------------------------------------------------------------------------
__global__ void k_select(const float* __restrict__ scores,
                         const float* __restrict__ off,
                         const float* __restrict__ rois,
                         const int*   __restrict__ imgshape)
{
    const int l   = blockIdx.x;
    const int cls = l + 1;

    float best  = -1e30f;
    int   bestr = 0x7fffffff;
    for (int r = threadIdx.x; r < R_ROIS; r += blockDim.x) {
        const float t = scores[r * NOBJ + cls] - g_logZ[r];
        if (t > best) { best = t; bestr = r; }
    }

    __shared__ float sb[256];
    __shared__ int   si[256];
    sb[threadIdx.x] = best;
    si[threadIdx.x] = bestr;
    __syncthreads();
    for (int st = blockDim.x >> 1; st > 0; st >>= 1) {
        if (threadIdx.x < st) {
            float ob = sb[threadIdx.x + st];
            int   oi = si[threadIdx.x + st];
            if (ob > sb[threadIdx.x] ||
                (ob == sb[threadIdx.x] && oi < si[threadIdx.x])) {
                sb[threadIdx.x] = ob; si[threadIdx.x] = oi;
            }
        }
        __syncthreads();
    }

    if (threadIdx.x == 0) {
        const int r = si[0];
        const float img0 = (float)imgshape[0];
        const float img1 = (float)imgshape[1];
        const float sy = (float)HFE / img0;
        const float sx = (float)WFE / img1;
        const float y1 = rois[r * 4 + 0] * sy;
        const float x1 = rois[r * 4 + 1] * sx;
        const float y2 = rois[r * 4 + 2] * sy;
        const float x2 = rois[r * 4 + 3] * sx;
        const float dy = off[r * (NOBJ * 4) + cls * 4 + 0] * 0.1f;
        const float dx = off[r * (NOBJ * 4) + cls * 4 + 1] * 0.1f;
        const float dh = off[r * (NOBJ * 4) + cls * 4 + 2] * 0.2f;
        const float dw = off[r * (NOBJ * 4) + cls * 4 + 3] * 0.2f;
        const float h  = y2 - y1, w = x2 - x1;
        const float cy = y1 + 0.5f * h, cx = x1 + 0.5f * w;
        const float cy2 = dy * h + cy, cx2 = dx * w + cx;
        const float h2 = expf(dh) * h, w2 = expf(dw) * w;
        float by1 = fminf(fmaxf(cy2 - 0.5f * h2, 0.0f), (float)HFE);
        float bx1 = fminf(fmaxf(cx2 - 0.5f * w2, 0.0f), (float)WFE);
        float by2 = fminf(fmaxf(cy2 + 0.5f * h2, 0.0f), (float)HFE);
        float bx2 = fminf(fmaxf(cx2 + 0.5f * w2, 0.0f), (float)WFE);
        g_kept[l][0] = by1; g_kept[l][1] = bx1;
        g_kept[l][2] = by2; g_kept[l][3] = bx2;
        if (l == HUMAN_LBL) {
            g_hbox[0] = by1; g_hbox[1] = bx1;
            g_hbox[2] = by2; g_hbox[3] = bx2;
        }
    }
}

// ---------------------------------------------------------------------------
// Kernel 2: chainer-style RoIPooling2D on the human box
// ---------------------------------------------------------------------------
__global__ void k_roipool(const float* __restrict__ x)
{
    const int idx = blockIdx.x * blockDim.x + threadIdx.x;
    if (idx >= D1) return;
    const int c  = idx / 49;
    const int ph = (idx % 49) / 7;
    const int pw = idx % 7;

    const float y1 = g_hbox[0], x1 = g_hbox[1], y2 = g_hbox[2], x2 = g_hbox[3];
    const int xmin = (int)rintf(x1 * 0.0625f);
    const int ymin = (int)rintf(y1 * 0.0625f);
    const int xmax = (int)rintf(x2 * 0.0625f);
    const int ymax = (int)rintf(y2 * 0.0625f);
    const float rw = (float)max(xmax - xmin + 1, 1);
    const float rh = (float)max(ymax - ymin + 1, 1);

    int hs = ymin + (int)floorf((float)ph * rh / 7.0f);
    int he = ymin + (int)ceilf((float)(ph + 1) * rh / 7.0f);
    int ws = xmin + (int)floorf((float)pw * rw / 7.0f);
    int we = xmin + (int)ceilf((float)(pw + 1) * rw / 7.0f);
    hs = min(max(hs, 0), HFE); he = min(max(he, 0), HFE);
    ws = min(max(ws, 0), WFE); we = min(max(we, 0), WFE);

    float m = -1e30f;
    for (int yy = hs; yy < he; yy++)
        for (int xx = ws; xx < we; xx++)
            m = fmaxf(m, x[c * (HFE * WFE) + yy * WFE + xx]);
    g_feat[idx] = (hs < he && ws < we) ? ((m <= -0.5e30f) ? 0.0f : m) : 0.0f;
}

// ---------------------------------------------------------------------------
// Kernel 3: GEMV1 split-K, float4 streaming loads + W2 L2-prefetch blocks.
// grid (4, SPLIT1 + PREF_BLKS/4), block 256.
//  - y <  SPLIT1 : compute.  j4 = bx*256+tid  (columns [0,1024) float4)
//  - y >= SPLIT1 : prefetch W2 into L2 (normal priority; W1 uses __ldcs)
// ---------------------------------------------------------------------------
__global__ void k_gemv1(const float4* __restrict__ W1,
                        const float4* __restrict__ W2)
{
    if (blockIdx.y < SPLIT1) {
        const int j4 = blockIdx.x * 256 + threadIdx.x;   // float4 column
        const int i0 = blockIdx.y * ROWS1;

        __shared__ float sf[ROWS1];
        for (int t = threadIdx.x; t < ROWS1; t += 256) sf[t] = g_feat[i0 + t];
        __syncthreads();

        float4 acc = make_float4(0.f, 0.f, 0.f, 0.f);
        const float4* __restrict__ w = W1 + (size_t)i0 * DH4 + j4;
        #pragma unroll 8
        for (int i = 0; i < ROWS1; i++) {
            const float4 v = __ldcs(&w[(size_t)i * DH4]);
            const float  s = sf[i];
            acc.x += s * v.x; acc.y += s * v.y;
            acc.z += s * v.z; acc.w += s * v.w;
        }
        g_part1[blockIdx.y * DH4 + j4] = acc;
    } else {
        // W2 prefetch: 256 blocks x 256 threads x 64 float4 = 64 MiB
        const int pid = blockIdx.x * (PREF_BLKS / 4) + (blockIdx.y - SPLIT1);
        const size_t base = (size_t)pid * PREF_PER_BLK + threadIdx.x;
        float acc = 0.0f;
        #pragma unroll 8
        for (int i = 0; i < PREF_PER_THR; i++) {
            const float4 v = __ldg(&W2[base + (size_t)i * 256]);
            acc += v.x + v.y + v.z + v.w;
        }
        g_sink[pid * 256 + threadIdx.x] = acc;   // DCE guard, never read
    }
}

// ---------------------------------------------------------------------------
// Kernel 4: reduce1. 64 blocks x 256 threads
// ---------------------------------------------------------------------------
__global__ void k_reduce1(const float* __restrict__ b1)
{
    const int jl = threadIdx.x & 63;
    const int kq = threadIdx.x >> 6;
    const int j  = blockIdx.x * 64 + jl;
    const float* p1 = (const float*)g_part1;

    float s = 0.0f;
    #pragma unroll
    for (int k = 0; k < SPLIT1 / 4; k++)
        s += p1[(kq * (SPLIT1 / 4) + k) * DH + j];

    __shared__ float sm[4][64];
    sm[kq][jl] = s;
    __syncthreads();
    if (kq == 0) {
        float t = sm[0][jl] + sm[1][jl] + sm[2][jl] + sm[3][jl] + b1[j];
        g_h1[j] = fmaxf(t, 0.0f);
    }
}

// ---------------------------------------------------------------------------
// Kernel 5: GEMV2 split-K, float4 (W2 should be L2-resident).
// grid (4, SPLIT2), block 256.
// ---------------------------------------------------------------------------
__global__ void k_gemv2(const float4* __restrict__ W2)
{
    const int j4 = blockIdx.x * 256 + threadIdx.x;
    const int i0 = blockIdx.y * ROWS2;

    __shared__ float sf[ROWS2];
    if (threadIdx.x < ROWS2) sf[threadIdx.x] = g_h1[i0 + threadIdx.x];
    __syncthreads();

    float4 acc = make_float4(0.f, 0.f, 0.f, 0.f);
    const float4* __restrict__ w = W2 + (size_t)i0 * DH4 + j4;
    #pragma unroll 8
    for (int i = 0; i < ROWS2; i++) {
        const float4 v = __ldg(&w[(size_t)i * DH4]);
        const float  s = sf[i];
        acc.x += s * v.x; acc.y += s * v.y;
        acc.z += s * v.z; acc.w += s * v.w;
    }
    g_part2[blockIdx.y * DH4 + j4] = acc;
}

// ---------------------------------------------------------------------------
// Kernel 6: reduce2. 64 blocks x 256 threads
// ---------------------------------------------------------------------------
__global__ void k_reduce2(const float* __restrict__ b2)
{
    const int jl = threadIdx.x & 63;
    const int kq = threadIdx.x >> 6;
    const int j  = blockIdx.x * 64 + jl;
    const float* p2 = (const float*)g_part2;

    float s = 0.0f;
    #pragma unroll
    for (int k = 0; k < SPLIT2 / 4; k++)
        s += p2[(kq * (SPLIT2 / 4) + k) * DH + j];

    __shared__ float sm[4][64];
    sm[kq][jl] = s;
    __syncthreads();
    if (kq == 0) {
        float t = sm[0][jl] + sm[1][jl] + sm[2][jl] + sm[3][jl] + b2[j];
        g_fc7[j] = fmaxf(t, 0.0f);
    }
}

// ---------------------------------------------------------------------------
// Kernel 7: heads. 31 blocks (4 loc + 27 act), 256 threads each.
// ---------------------------------------------------------------------------
__global__ void k_heads(const float* __restrict__ Wloc, const float* __restrict__ bloc,
                        const float* __restrict__ Wact, const float* __restrict__ bact,
                        float* __restrict__ out)
{
    const int o = blockIdx.x;
    float acc = 0.0f;
    if (o < 4) {
        for (int i = threadIdx.x; i < DH; i += 256)
            acc += g_fc7[i] * Wloc[i * 4 + o];
    } else {
        const int a = o - 4;
        for (int i = threadIdx.x; i < DH; i += 256)
            acc += g_fc7[i] * Wact[i * NACT + a];
    }
    __shared__ float sb[256];
    sb[threadIdx.x] = acc;
    __syncthreads();
    for (int st = 128; st > 0; st >>= 1) {
        if (threadIdx.x < st) sb[threadIdx.x] += sb[threadIdx.x + st];
        __syncthreads();
    }
    if (threadIdx.x == 0) {
        if (o < 4) g_loc[o] = sb[0] + bloc[o];
        else       out[8 + (o - 4)] = sb[0] + bact[o - 4];
    }
}

// ---------------------------------------------------------------------------
// Kernel 8: gaussian object selection + output assembly
// ---------------------------------------------------------------------------
__global__ void k_final(const int* __restrict__ imgshape, float* __restrict__ out)
{
    if (threadIdx.x != 0) return;
    const float img0 = (float)imgshape[0];
    const float img1 = (float)imgshape[1];

    const float hb0 = g_hbox[0], hb1 = g_hbox[1], hb2 = g_hbox[2], hb3 = g_hbox[3];
    const float hw_ = hb3 - hb1, hh_ = hb2 - hb0;
    const float h4x = 0.5f * hw_, h4y = 0.5f * hh_;
    const float hw = fmaxf(hw_, 1e-3f), hh = fmaxf(hh_, 1e-3f);

    const float mw = g_loc[3] - g_loc[1], mh = g_loc[2] - g_loc[0];
    const float mu0 = 0.5f * mw, mu1 = 0.5f * mh, mu2 = mw, mu3 = mh;

    float best = -1.0f;
    int   bl   = 0;
    for (int l = 0; l < 20; l++) {
        if (l == HUMAN_LBL) continue;
        const float b0 = g_kept[l][0], b1 = g_kept[l][1];
        const float b2 = g_kept[l][2], b3 = g_kept[l][3];
        const float cw_ = b3 - b1, ch_ = b2 - b0;
        const float cx = 0.5f * cw_, cy = 0.5f * ch_;
        const float cw = fmaxf(cw_, 1e-3f), ch = fmaxf(ch_, 1e-3f);
        const float d0 = (cx - h4x) / hw - mu0;
        const float d1 = (cy - h4y) / hh - mu1;
        const float d2 = logf(cw / hw) - mu2;
        const float d3 = logf(ch / hh) - mu3;
        const float gau = expf(-(d0 * d0 + d1 * d1 + d2 * d2 + d3 * d3) /
                               (2.0f * 0.3f * 0.3f));
        if (gau > best) { best = gau; bl = l; }
    }

    const float invy = img0 / (float)HFE;
    const float invx = img1 / (float)WFE;
    out[0] = hb0 * invy; out[1] = hb1 * invx;
    out[2] = hb2 * invy; out[3] = hb3 * invx;
    out[4] = g_kept[bl][0] * invy; out[5] = g_kept[bl][1] * invx;
    out[6] = g_kept[bl][2] * invy; out[7] = g_kept[bl][3] * invx;
    out[35] = (float)HFE / img0;
}

// ---------------------------------------------------------------------------
extern "C" void kernel_launch(void* const* d_in, const int* in_sizes, int n_in,
                              void* d_out, int out_size)
{
    const float* x        = (const float*)d_in[0];
    const float* pscores  = (const float*)d_in[1];
    const float* poff     = (const float*)d_in[2];
    const float* rois     = (const float*)d_in[3];
    const int*   imgshape = (const int*)  d_in[4];
    const float* W1       = (const float*)d_in[5];
    const float* b1       = (const float*)d_in[6];
    const float* W2       = (const float*)d_in[7];
    const float* b2       = (const float*)d_in[8];
    const float* Wloc     = (const float*)d_in[9];
    const float* bloc     = (const float*)d_in[10];
    const float* Wact     = (const float*)d_in[11];
    const float* bact     = (const float*)d_in[12];
    float* out = (float*)d_out;

    k_softprep<<<(R_ROIS + 255) / 256, 256>>>(pscores);
    k_select  <<<20, 256>>>(pscores, poff, rois, imgshape);
    k_roipool <<<(D1 + 255) / 256, 256>>>(x);
    k_gemv1   <<<dim3(4, SPLIT1 + PREF_BLKS / 4), 256>>>((const float4*)W1,
                                                         (const float4*)W2);
    k_reduce1 <<<64, 256>>>(b1);
    k_gemv2   <<<dim3(4, SPLIT2), 256>>>((const float4*)W2);
    k_reduce2 <<<64, 256>>>(b2);
    k_heads   <<<31, 256>>>(Wloc, bloc, Wact, bact, out);
    k_final   <<<1, 32>>>(imgshape, out);
}